// round 1
// baseline (speedup 1.0000x reference)
#include <cuda_runtime.h>
#include <math.h>

#define LL 256
#define BB 256
#define HH 256
#define CC 16
#define YY 32
#define NSTEPS 255
#define NCTA 128

// ---------------- global scratch (static allocation, allowed) ----------------
__device__ float g_zT[HH * BB];                 // z transposed: zT[h][b]
__device__ float g_hidT[HH * BB];               // hid transposed: hidT[h][b]
__device__ float g_dstep[NSTEPS * BB * CC];     // folded dt * dXdt per step: [k][b][c]
__device__ float g_zseq[LL * HH * BB];          // z_seq transposed per step: [l][h][b]
__device__ unsigned g_bar_count;

// ---------------- packed f32x2 helpers (sm_103a FFMA2) ----------------
#define FMA2(acc, a, b) asm("fma.rn.f32x2 %0, %1, %2, %0;" : "+l"(acc) : "l"(a), "l"(b))
#define PACK2(r, lo, hi) asm("mov.b64 %0, {%1, %2};" : "=l"(r) : "f"(lo), "f"(hi))
#define UNPACK2(lo, hi, r) asm("mov.b64 {%0, %1}, %2;" : "=f"(lo), "=f"(hi) : "l"(r))

// ---------------- grid barrier (monotonic count; reset by prep kernel) -------
__device__ __forceinline__ void gridbar(unsigned target) {
    __threadfence();                 // drain my stores to L2 (release)
    __syncthreads();
    if (threadIdx.x == 0) {
        atomicAdd(&g_bar_count, 1u);
        volatile unsigned* p = &g_bar_count;
        while (*p < target) { }
    }
    __syncthreads();
    __threadfence();                 // CCTL.IVALL: invalidate L1D (acquire)
}

// ---------------- prep: fold Hermite derivative + dt into per-step vectors ---
__device__ __forceinline__ float Xv(const float* ts, const float* us, int l, int b, int c) {
    return (c == 0) ? ts[(size_t)l * BB + b]
                    : us[((size_t)l * BB + b) * (CC - 1) + (c - 1)];
}

__global__ void prep_kernel(const float* __restrict__ ts, const float* __restrict__ us) {
    int k = blockIdx.x;      // step 0..254
    int b = threadIdx.x;     // batch
    if (k == 0 && b == 0) g_bar_count = 0u;

    float s  = ts[(size_t)k * BB];
    float dt = ts[(size_t)(k + 1) * BB] - s;
    int idx = (int)floorf(s);
    idx = idx < 0 ? 0 : (idx > LL - 2 ? LL - 2 : idx);
    float tau = s - (float)idx;
    float h00p = 6.f * tau * tau - 6.f * tau;
    float h10p = 3.f * tau * tau - 4.f * tau + 1.f;
    float h11p = 3.f * tau * tau - 2.f * tau;

    float* dst = g_dstep + ((size_t)k * BB + b) * CC;
    #pragma unroll
    for (int c = 0; c < CC; c++) {
        float x_i  = Xv(ts, us, idx, b, c);
        float x_ip = Xv(ts, us, idx + 1, b, c);
        float di   = (idx == 0) ? (x_ip - x_i) : (x_i - Xv(ts, us, idx - 1, b, c));
        float dip  = x_ip - x_i;
        float val  = h00p * (x_i - x_ip) + h10p * di + h11p * dip;
        dst[c] = dt * val;
    }
}

// ---------------- persistent scan kernel -------------------------------------
// CTA j owns: W2 columns [32j, 32j+32) in smem, W1 columns {2j, 2j+1},
// and z rows (h = 2j, 2j+1) for all 256 batches (kept in registers).
__global__ void __launch_bounds__(256, 1)
scan_kernel(const float* __restrict__ W1, const float* __restrict__ b1,
            const float* __restrict__ W2, const float* __restrict__ b2,
            const float* __restrict__ h0) {
    const int t = threadIdx.x;    // batch index b
    const int j = blockIdx.x;     // CTA id 0..127
    __shared__ float  w2s[256][32];   // 32 KB: W2 slice [k][n']
    __shared__ float2 w1s[256];       // W1[k][{2j,2j+1}]
    __shared__ float  b2s[32];
    __shared__ float  b1s[2];

    // one-time weight staging
    {
        const float4* src = (const float4*)(W2 + (size_t)t * (HH * CC) + j * 32);
        float4* dst = (float4*)(&w2s[t][0]);
        #pragma unroll
        for (int q = 0; q < 8; q++) dst[q] = src[q];
        w1s[t] = *(const float2*)(W1 + (size_t)t * HH + 2 * j);
        if (t < 32) b2s[t] = b2[j * 32 + t];
        if (t < 2)  b1s[t] = b1[2 * j + t];
    }

    const int h0i = 2 * j, h1i = 2 * j + 1;
    float zc0 = h0[(size_t)t * HH + h0i];
    float zc1 = h0[(size_t)t * HH + h1i];
    g_zT[h0i * BB + t] = zc0;
    g_zT[h1i * BB + t] = zc1;
    g_zseq[(size_t)h0i * BB + t] = zc0;     // z_seq[0]
    g_zseq[(size_t)h1i * BB + t] = zc1;

    unsigned ep = 0;
    gridbar((++ep) * NCTA);   // z init + weights visible everywhere

    for (int step = 0; step < NSTEPS; ++step) {
        // ---- stage 1: hid[:, 2j:2j+2] = relu(z @ W1slice + b1slice) ----
        float a0, a1;
        {
            unsigned long long acc01;
            PACK2(acc01, b1s[0], b1s[1]);
            const float* zp = g_zT + t;
            const unsigned long long* wp = (const unsigned long long*)w1s;
            #pragma unroll 8
            for (int k = 0; k < HH; k++) {
                float zv = zp[(size_t)k * BB];
                unsigned long long aa; PACK2(aa, zv, zv);
                FMA2(acc01, aa, wp[k]);
            }
            UNPACK2(a0, a1, acc01);
        }
        a0 = fmaxf(a0, 0.f);
        a1 = fmaxf(a1, 0.f);
        g_hidT[h0i * BB + t] = a0;
        g_hidT[h1i * BB + t] = a1;
        gridbar((++ep) * NCTA);

        // ---- stage 2: G[b, nslice] = hid[b,:] @ W2slice + b2slice ----
        unsigned long long acc[16];
        #pragma unroll
        for (int p = 0; p < 16; p++) PACK2(acc[p], b2s[2 * p], b2s[2 * p + 1]);
        {
            const float* hp = g_hidT + t;
            #pragma unroll 4
            for (int k = 0; k < HH; k++) {
                float hv = hp[(size_t)k * BB];
                unsigned long long aa; PACK2(aa, hv, hv);
                const ulonglong2* wp = (const ulonglong2*)(&w2s[k][0]);
                #pragma unroll
                for (int q = 0; q < 8; q++) {
                    ulonglong2 w = wp[q];
                    FMA2(acc[2 * q],     aa, w.x);
                    FMA2(acc[2 * q + 1], aa, w.y);
                }
            }
        }

        // ---- dz contraction over C; dt already folded into g_dstep ----
        float d[16];
        {
            const float4* dp = (const float4*)(g_dstep + ((size_t)step * BB + t) * CC);
            float4 v0 = dp[0], v1 = dp[1], v2 = dp[2], v3 = dp[3];
            d[0]=v0.x; d[1]=v0.y; d[2]=v0.z; d[3]=v0.w;
            d[4]=v1.x; d[5]=v1.y; d[6]=v1.z; d[7]=v1.w;
            d[8]=v2.x; d[9]=v2.y; d[10]=v2.z; d[11]=v2.w;
            d[12]=v3.x; d[13]=v3.y; d[14]=v3.z; d[15]=v3.w;
        }
        float dz0 = 0.f, dz1 = 0.f;
        #pragma unroll
        for (int p = 0; p < 8; p++) {
            float lo, hi; UNPACK2(lo, hi, acc[p]);
            dz0 += tanhf(lo) * d[2 * p] + tanhf(hi) * d[2 * p + 1];
        }
        #pragma unroll
        for (int p = 8; p < 16; p++) {
            float lo, hi; UNPACK2(lo, hi, acc[p]);
            dz1 += tanhf(lo) * d[2 * p - 16] + tanhf(hi) * d[2 * p - 15];
        }
        zc0 += dz0;
        zc1 += dz1;
        g_zT[h0i * BB + t] = zc0;
        g_zT[h1i * BB + t] = zc1;
        g_zseq[(size_t)(step + 1) * (HH * BB) + h0i * BB + t] = zc0;
        g_zseq[(size_t)(step + 1) * (HH * BB) + h1i * BB + t] = zc1;
        gridbar((++ep) * NCTA);
    }
}

// ---------------- final projection: tanh(z_seq @ dW1 + db1) @ dW2 + db2 ------
#define JCH 32
__global__ void __launch_bounds__(256, 2)
final_kernel(const float* __restrict__ dW1, const float* __restrict__ db1,
             const float* __restrict__ dW2, const float* __restrict__ db2,
             float* __restrict__ out) {
    const int l = blockIdx.x, t = threadIdx.x;  // t = batch b
    __shared__ float w1s[256 * JCH];   // chunk [h][jj] 32 KB
    __shared__ float w2s[JCH * 32];    // chunk [jj][y]  4 KB
    __shared__ float db1s[JCH];

    unsigned long long oacc[16];
    #pragma unroll
    for (int q = 0; q < 16; q++) PACK2(oacc[q], db2[2 * q], db2[2 * q + 1]);

    for (int ch = 0; ch < 512 / JCH; ++ch) {
        const int j0 = ch * JCH;
        {
            const float4* src = (const float4*)(dW1 + (size_t)t * 512 + j0);
            float4* dst = (float4*)(w1s + t * JCH);
            #pragma unroll
            for (int q = 0; q < JCH / 4; q++) dst[q] = src[q];
            for (int q = t; q < JCH * 32; q += 256) w2s[q] = dW2[(size_t)j0 * 32 + q];
            if (t < JCH) db1s[t] = db1[j0 + t];
        }
        __syncthreads();

        unsigned long long hacc[JCH / 2];
        #pragma unroll
        for (int p = 0; p < JCH / 2; p++) PACK2(hacc[p], db1s[2 * p], db1s[2 * p + 1]);
        {
            const float* zp = g_zseq + (size_t)l * (HH * BB) + t;
            #pragma unroll 4
            for (int k = 0; k < HH; k++) {
                float zv = zp[(size_t)k * BB];
                unsigned long long aa; PACK2(aa, zv, zv);
                const ulonglong2* wp = (const ulonglong2*)(w1s + k * JCH);
                #pragma unroll
                for (int q = 0; q < JCH / 4; q++) {
                    ulonglong2 w = wp[q];
                    FMA2(hacc[2 * q],     aa, w.x);
                    FMA2(hacc[2 * q + 1], aa, w.y);
                }
            }
        }
        #pragma unroll
        for (int p = 0; p < JCH / 2; p++) {
            float lo, hi; UNPACK2(lo, hi, hacc[p]);
            float t0 = tanhf(lo), t1 = tanhf(hi);
            unsigned long long aa0, aa1; PACK2(aa0, t0, t0); PACK2(aa1, t1, t1);
            const unsigned long long* r0 = (const unsigned long long*)(w2s + (2 * p) * 32);
            const unsigned long long* r1 = (const unsigned long long*)(w2s + (2 * p + 1) * 32);
            #pragma unroll
            for (int q = 0; q < 16; q++) FMA2(oacc[q], aa0, r0[q]);
            #pragma unroll
            for (int q = 0; q < 16; q++) FMA2(oacc[q], aa1, r1[q]);
        }
        __syncthreads();
    }

    float* op = out + ((size_t)l * BB + t) * YY;
    #pragma unroll
    for (int q = 0; q < 16; q++) {
        float lo, hi; UNPACK2(lo, hi, oacc[q]);
        op[2 * q] = lo; op[2 * q + 1] = hi;
    }
}

// ---------------- launch ------------------------------------------------------
extern "C" void kernel_launch(void* const* d_in, const int* in_sizes, int n_in,
                              void* d_out, int out_size) {
    const float* ts  = (const float*)d_in[0];
    const float* us  = (const float*)d_in[1];
    const float* h0  = (const float*)d_in[2];
    const float* W1  = (const float*)d_in[3];
    const float* b1  = (const float*)d_in[4];
    const float* W2  = (const float*)d_in[5];
    const float* b2  = (const float*)d_in[6];
    const float* dW1 = (const float*)d_in[7];
    const float* db1 = (const float*)d_in[8];
    const float* dW2 = (const float*)d_in[9];
    const float* db2 = (const float*)d_in[10];

    prep_kernel<<<NSTEPS, 256>>>(ts, us);
    scan_kernel<<<NCTA, 256>>>(W1, b1, W2, b2, h0);
    final_kernel<<<LL, 256>>>(dW1, db1, dW2, db2, (float*)d_out);
}

// round 3
// speedup vs baseline: 1.1957x; 1.1957x over previous
#include <cuda_runtime.h>
#include <cstdint>
#include <math.h>

#define LL 256
#define BB 256
#define HH 256
#define CC 16
#define YY 32
#define NSTEPS 255
#define NCTA 128
#define CHUNK 32
#define NCHUNKS (HH / CHUNK)   // 8
#define CHUNK_FLOATS (CHUNK * BB)   // 8192 floats = 32 KB

// ---------------- global scratch ----------------
__device__ float g_zT[HH * BB];                 // z transposed: zT[h][b]
__device__ float g_hidT[HH * BB];               // hid transposed: hidT[h][b]
__device__ float g_dstep[NSTEPS * BB * CC];     // folded dt * dXdt per step
__device__ float g_zseq[LL * HH * BB];          // z_seq transposed per step
__device__ unsigned g_bar_count;

// ---------------- packed f32x2 helpers (sm_103a FFMA2) ----------------
#define FMA2(acc, a, b) asm("fma.rn.f32x2 %0, %1, %2, %0;" : "+l"(acc) : "l"(a), "l"(b))
#define PACK2(r, lo, hi) asm("mov.b64 %0, {%1, %2};" : "=l"(r) : "f"(lo), "f"(hi))
#define UNPACK2(lo, hi, r) asm("mov.b64 {%0, %1}, %2;" : "=f"(lo), "=f"(hi) : "l"(r))

// ---------------- cp.async helpers ----------------
__device__ __forceinline__ void cpasync16(unsigned int saddr, const void* g) {
    asm volatile("cp.async.cg.shared.global [%0], [%1], 16;" :: "r"(saddr), "l"(g));
}
#define CP_COMMIT() asm volatile("cp.async.commit_group;")
#define CP_WAIT(n)  asm volatile("cp.async.wait_group %0;" :: "n"(n))

// load one 32x256 f32 chunk (32 KB) into smem buffer; 8 x 16B per thread
__device__ __forceinline__ void load_chunk(float* dstbuf, const float* src, int t) {
    unsigned int s = (unsigned int)__cvta_generic_to_shared(dstbuf) + (unsigned int)t * 16u;
    const float* g = src + t * 4;
    #pragma unroll
    for (int i = 0; i < 8; i++)
        cpasync16(s + i * 4096u, g + i * 1024);
    CP_COMMIT();
}

// ---------------- grid barrier (monotonic count; reset by prep kernel) -------
__device__ __forceinline__ void gridbar(unsigned target) {
    __threadfence();                 // release: drain my stores to L2
    __syncthreads();
    if (threadIdx.x == 0) {
        atomicAdd(&g_bar_count, 1u);
        volatile unsigned* p = &g_bar_count;
        while (*p < target) { __nanosleep(40); }
    }
    __syncthreads();
    __threadfence();                 // acquire: CCTL.IVALL invalidates L1D
}

// ---------------- prep: fold Hermite derivative + dt into per-step vectors ---
__device__ __forceinline__ float Xv(const float* ts, const float* us, int l, int b, int c) {
    return (c == 0) ? ts[(size_t)l * BB + b]
                    : us[((size_t)l * BB + b) * (CC - 1) + (c - 1)];
}

__global__ void prep_kernel(const float* __restrict__ ts, const float* __restrict__ us) {
    int k = blockIdx.x;      // step 0..254
    int b = threadIdx.x;     // batch
    if (k == 0 && b == 0) g_bar_count = 0u;

    float s  = ts[(size_t)k * BB];
    float dt = ts[(size_t)(k + 1) * BB] - s;
    int idx = (int)floorf(s);
    idx = idx < 0 ? 0 : (idx > LL - 2 ? LL - 2 : idx);
    float tau = s - (float)idx;
    float h00p = 6.f * tau * tau - 6.f * tau;
    float h10p = 3.f * tau * tau - 4.f * tau + 1.f;
    float h11p = 3.f * tau * tau - 2.f * tau;

    float* dst = g_dstep + ((size_t)k * BB + b) * CC;
    #pragma unroll
    for (int c = 0; c < CC; c++) {
        float x_i  = Xv(ts, us, idx, b, c);
        float x_ip = Xv(ts, us, idx + 1, b, c);
        float di   = (idx == 0) ? (x_ip - x_i) : (x_i - Xv(ts, us, idx - 1, b, c));
        float dip  = x_ip - x_i;
        float val  = h00p * (x_i - x_ip) + h10p * di + h11p * dip;
        dst[c] = dt * val;
    }
}

// ---------------- persistent scan kernel -------------------------------------
// CTA j owns: W2 columns [32j, 32j+32) in smem, W1 columns {2j, 2j+1},
// z rows (h = 2j, 2j+1). Activation matrices streamed via cp.async pipeline.
// Dynamic smem layout (floats):
//   [0, 8192)        w2s   : W2 slice [k][n']   (32 KB)
//   [8192, 8704)     w1s   : float2 W1[k]       (2 KB)
//   [8704, 25088)    xbuf  : 2 x 32x256 chunk   (64 KB)
//   [25088, 25120)   b2s
//   [25120, 25122)   b1s
#define SMEM_FLOATS 25128
#define SMEM_BYTES  (SMEM_FLOATS * 4)

__global__ void __launch_bounds__(256, 1)
scan_kernel(const float* __restrict__ W1, const float* __restrict__ b1,
            const float* __restrict__ W2, const float* __restrict__ b2,
            const float* __restrict__ h0) {
    extern __shared__ float smem[];
    float*  w2s = smem;
    float2* w1s = (float2*)(smem + 8192);
    float*  xbuf = smem + 8704;
    float*  b2s = smem + 25088;
    float*  b1s = smem + 25120;

    const int t = threadIdx.x;    // batch index b
    const int j = blockIdx.x;     // CTA id 0..127

    // one-time weight staging
    {
        const float4* src = (const float4*)(W2 + (size_t)t * (HH * CC) + j * 32);
        float4* dst = (float4*)(w2s + t * 32);
        #pragma unroll
        for (int q = 0; q < 8; q++) dst[q] = src[q];
        w1s[t] = *(const float2*)(W1 + (size_t)t * HH + 2 * j);
        if (t < 32) b2s[t] = b2[j * 32 + t];
        if (t < 2)  b1s[t] = b1[2 * j + t];
    }

    const int h0i = 2 * j, h1i = 2 * j + 1;
    float zc0 = h0[(size_t)t * HH + h0i];
    float zc1 = h0[(size_t)t * HH + h1i];
    g_zT[h0i * BB + t] = zc0;
    g_zT[h1i * BB + t] = zc1;
    g_zseq[(size_t)h0i * BB + t] = zc0;     // z_seq[0]
    g_zseq[(size_t)h1i * BB + t] = zc1;

    unsigned ep = 0;
    gridbar((++ep) * NCTA);   // z init + weights visible everywhere

    for (int step = 0; step < NSTEPS; ++step) {
        // ---- stage 1: hid[:, 2j:2j+2] = relu(z @ W1slice + b1slice) ----
        float a0, a1;
        {
            unsigned long long acc01;
            PACK2(acc01, b1s[0], b1s[1]);
            const unsigned long long* wp = (const unsigned long long*)w1s;

            load_chunk(xbuf, g_zT, t);
            for (int c = 0; c < NCHUNKS; ++c) {
                if (c + 1 < NCHUNKS)
                    load_chunk(xbuf + ((c + 1) & 1) * CHUNK_FLOATS,
                               g_zT + (c + 1) * CHUNK_FLOATS, t);
                if (c + 1 < NCHUNKS) { CP_WAIT(1); } else { CP_WAIT(0); }
                __syncthreads();
                const float* buf = xbuf + (c & 1) * CHUNK_FLOATS;
                #pragma unroll 8
                for (int kk = 0; kk < CHUNK; kk++) {
                    float zv = buf[kk * BB + t];
                    unsigned long long aa; PACK2(aa, zv, zv);
                    FMA2(acc01, aa, wp[c * CHUNK + kk]);
                }
                __syncthreads();
            }
            UNPACK2(a0, a1, acc01);
        }
        a0 = fmaxf(a0, 0.f);
        a1 = fmaxf(a1, 0.f);
        g_hidT[h0i * BB + t] = a0;
        g_hidT[h1i * BB + t] = a1;
        gridbar((++ep) * NCTA);

        // ---- stage 2: G[b, nslice] = hid[b,:] @ W2slice + b2slice ----
        unsigned long long acc[16];
        #pragma unroll
        for (int p = 0; p < 16; p++) PACK2(acc[p], b2s[2 * p], b2s[2 * p + 1]);
        {
            load_chunk(xbuf, g_hidT, t);
            for (int c = 0; c < NCHUNKS; ++c) {
                if (c + 1 < NCHUNKS)
                    load_chunk(xbuf + ((c + 1) & 1) * CHUNK_FLOATS,
                               g_hidT + (c + 1) * CHUNK_FLOATS, t);
                if (c + 1 < NCHUNKS) { CP_WAIT(1); } else { CP_WAIT(0); }
                __syncthreads();
                const float* buf = xbuf + (c & 1) * CHUNK_FLOATS;
                #pragma unroll 8
                for (int kk = 0; kk < CHUNK; kk++) {
                    float hv = buf[kk * BB + t];
                    unsigned long long aa; PACK2(aa, hv, hv);
                    const ulonglong2* wp2 = (const ulonglong2*)(w2s + (c * CHUNK + kk) * 32);
                    #pragma unroll
                    for (int q = 0; q < 8; q++) {
                        ulonglong2 w = wp2[q];
                        FMA2(acc[2 * q],     aa, w.x);
                        FMA2(acc[2 * q + 1], aa, w.y);
                    }
                }
                __syncthreads();
            }
        }

        // ---- dz contraction over C; dt already folded into g_dstep ----
        float d[16];
        {
            const float4* dp = (const float4*)(g_dstep + ((size_t)step * BB + t) * CC);
            float4 v0 = dp[0], v1 = dp[1], v2 = dp[2], v3 = dp[3];
            d[0]=v0.x; d[1]=v0.y; d[2]=v0.z; d[3]=v0.w;
            d[4]=v1.x; d[5]=v1.y; d[6]=v1.z; d[7]=v1.w;
            d[8]=v2.x; d[9]=v2.y; d[10]=v2.z; d[11]=v2.w;
            d[12]=v3.x; d[13]=v3.y; d[14]=v3.z; d[15]=v3.w;
        }
        float dz0 = 0.f, dz1 = 0.f;
        #pragma unroll
        for (int p = 0; p < 8; p++) {
            float lo, hi; UNPACK2(lo, hi, acc[p]);
            dz0 += tanhf(lo) * d[2 * p] + tanhf(hi) * d[2 * p + 1];
        }
        #pragma unroll
        for (int p = 8; p < 16; p++) {
            float lo, hi; UNPACK2(lo, hi, acc[p]);
            dz1 += tanhf(lo) * d[2 * p - 16] + tanhf(hi) * d[2 * p - 15];
        }
        zc0 += dz0;
        zc1 += dz1;
        g_zT[h0i * BB + t] = zc0;
        g_zT[h1i * BB + t] = zc1;
        g_zseq[(size_t)(step + 1) * (HH * BB) + h0i * BB + t] = zc0;
        g_zseq[(size_t)(step + 1) * (HH * BB) + h1i * BB + t] = zc1;
        gridbar((++ep) * NCTA);
    }
}

// ---------------- final projection: tanh(z_seq @ dW1 + db1) @ dW2 + db2 ------
#define JCH 32
__global__ void __launch_bounds__(256, 2)
final_kernel(const float* __restrict__ dW1, const float* __restrict__ db1,
             const float* __restrict__ dW2, const float* __restrict__ db2,
             float* __restrict__ out) {
    const int l = blockIdx.x, t = threadIdx.x;  // t = batch b
    __shared__ float w1s[256 * JCH];   // chunk [h][jj] 32 KB
    __shared__ float w2s[JCH * 32];    // chunk [jj][y]  4 KB
    __shared__ float db1s[JCH];

    unsigned long long oacc[16];
    #pragma unroll
    for (int q = 0; q < 16; q++) PACK2(oacc[q], db2[2 * q], db2[2 * q + 1]);

    for (int ch = 0; ch < 512 / JCH; ++ch) {
        const int j0 = ch * JCH;
        {
            const float4* src = (const float4*)(dW1 + (size_t)t * 512 + j0);
            float4* dst = (float4*)(w1s + t * JCH);
            #pragma unroll
            for (int q = 0; q < JCH / 4; q++) dst[q] = src[q];
            for (int q = t; q < JCH * 32; q += 256) w2s[q] = dW2[(size_t)j0 * 32 + q];
            if (t < JCH) db1s[t] = db1[j0 + t];
        }
        __syncthreads();

        unsigned long long hacc[JCH / 2];
        #pragma unroll
        for (int p = 0; p < JCH / 2; p++) PACK2(hacc[p], db1s[2 * p], db1s[2 * p + 1]);
        {
            const float* zp = g_zseq + (size_t)l * (HH * BB) + t;
            #pragma unroll 4
            for (int k = 0; k < HH; k++) {
                float zv = zp[(size_t)k * BB];
                unsigned long long aa; PACK2(aa, zv, zv);
                const ulonglong2* wp = (const ulonglong2*)(w1s + k * JCH);
                #pragma unroll
                for (int q = 0; q < JCH / 4; q++) {
                    ulonglong2 w = wp[q];
                    FMA2(hacc[2 * q],     aa, w.x);
                    FMA2(hacc[2 * q + 1], aa, w.y);
                }
            }
        }
        #pragma unroll
        for (int p = 0; p < JCH / 2; p++) {
            float lo, hi; UNPACK2(lo, hi, hacc[p]);
            float t0 = tanhf(lo), t1 = tanhf(hi);
            unsigned long long aa0, aa1; PACK2(aa0, t0, t0); PACK2(aa1, t1, t1);
            const unsigned long long* r0 = (const unsigned long long*)(w2s + (2 * p) * 32);
            const unsigned long long* r1 = (const unsigned long long*)(w2s + (2 * p + 1) * 32);
            #pragma unroll
            for (int q = 0; q < 16; q++) FMA2(oacc[q], aa0, r0[q]);
            #pragma unroll
            for (int q = 0; q < 16; q++) FMA2(oacc[q], aa1, r1[q]);
        }
        __syncthreads();
    }

    float* op = out + ((size_t)l * BB + t) * YY;
    #pragma unroll
    for (int q = 0; q < 16; q++) {
        float lo, hi; UNPACK2(lo, hi, oacc[q]);
        op[2 * q] = lo; op[2 * q + 1] = hi;
    }
}

// ---------------- launch ------------------------------------------------------
extern "C" void kernel_launch(void* const* d_in, const int* in_sizes, int n_in,
                              void* d_out, int out_size) {
    const float* ts  = (const float*)d_in[0];
    const float* us  = (const float*)d_in[1];
    const float* h0  = (const float*)d_in[2];
    const float* W1  = (const float*)d_in[3];
    const float* b1  = (const float*)d_in[4];
    const float* W2  = (const float*)d_in[5];
    const float* b2  = (const float*)d_in[6];
    const float* dW1 = (const float*)d_in[7];
    const float* db1 = (const float*)d_in[8];
    const float* dW2 = (const float*)d_in[9];
    const float* db2 = (const float*)d_in[10];

    cudaFuncSetAttribute(scan_kernel,
                         cudaFuncAttributeMaxDynamicSharedMemorySize, SMEM_BYTES);

    prep_kernel<<<NSTEPS, 256>>>(ts, us);
    scan_kernel<<<NCTA, 256, SMEM_BYTES>>>(W1, b1, W2, b2, h0);
    final_kernel<<<LL, 256>>>(dW1, db1, dW2, db2, (float*)d_out);
}